// round 8
// baseline (speedup 1.0000x reference)
#include <cuda_runtime.h>
#include <cstdint>
#include <math.h>

#define B_SZ   4096
#define F1     6272          // 32*14*14
#define HID    2048
#define NCLS   10
#define EPSV   1e-5f

// ---------------- static device scratch (no runtime allocation) ----------------
__device__ __align__(16) int8_t g_act[(size_t)B_SZ * F1];   // 25.7 MB, ±1
__device__ __align__(16) int8_t g_w2b[(size_t)HID  * F1];   // 12.8 MB, ±1
__device__ float g_part[(size_t)16 * B_SZ * NCLS];          // 2.6 MB partial logits
__device__ uint32_t g_wpA[96], g_wpB[96];                   // conv weight byte-packs
__device__ int      g_ithr[32];                             // integer sign thresholds

// =============================== helpers ===============================

__device__ __forceinline__ uint32_t smem_u32(const void* p) {
    return (uint32_t)__cvta_generic_to_shared(p);
}

__device__ __forceinline__ void cp16(uint32_t dst, const void* src) {
    asm volatile("cp.async.cg.shared.global [%0], [%1], 16;"
                 :: "r"(dst), "l"(src) : "memory");
}

__device__ __forceinline__ void mma_s8(int* d, const uint32_t* a, const uint32_t* b) {
    asm volatile(
        "mma.sync.aligned.m16n8k32.row.col.s32.s8.s8.s32 "
        "{%0,%1,%2,%3}, {%4,%5,%6,%7}, {%8,%9}, {%0,%1,%2,%3};"
        : "+r"(d[0]), "+r"(d[1]), "+r"(d[2]), "+r"(d[3])
        : "r"(a[0]), "r"(a[1]), "r"(a[2]), "r"(a[3]), "r"(b[0]), "r"(b[1]));
}

__device__ __forceinline__ void ldsm4(uint32_t* r, uint32_t addr) {
    asm volatile("ldmatrix.sync.aligned.m8n8.x4.shared.b16 {%0,%1,%2,%3}, [%4];"
                 : "=r"(r[0]), "=r"(r[1]), "=r"(r[2]), "=r"(r[3]) : "r"(addr));
}

// =============================== kernel 0: conv constants prep (once) ===============================

__global__ void __launch_bounds__(96) k_prep(
    const float* __restrict__ W1, const float* __restrict__ b1,
    const float* __restrict__ g1, const float* __restrict__ be1,
    const float* __restrict__ m1, const float* __restrict__ v1)
{
    int t = threadIdx.x;
    if (t < 96) {       // per-channel weight-row byte packs (A: bytes0-2, B: bytes1-3)
        int ch = t / 3, j = t % 3;
        const float* wr = W1 + ch * 9 + j * 3;
        uint32_t b0 = (uint8_t)(int8_t)(wr[0] >= 0.f ? 1 : -1);
        uint32_t bb = (uint8_t)(int8_t)(wr[1] >= 0.f ? 1 : -1);
        uint32_t b2 = (uint8_t)(int8_t)(wr[2] >= 0.f ? 1 : -1);
        g_wpA[t] = b0 | (bb << 8) | (b2 << 16);
        g_wpB[t] = (b0 << 8) | (bb << 16) | (b2 << 24);
    }
    if (t < 32) {
        // sign(BN(pool(conv)+b1)) == (mx >= thr), thr = m1 - be1*sqrt(v1+eps)/g1 - b1 (g1>0)
        // mx is an exact integer in [-9,9] => integer threshold ceil(thr) is exact.
        double sq = sqrt((double)v1[t] + (double)EPSV);
        double thr = (double)m1[t] - (double)be1[t] * sq / (double)g1[t] - (double)b1[t];
        g_ithr[t] = (int)ceil(thr);
    }
}

// =============================== kernel 1: W2 sign-pack (f32 -> int8 ±1) ===============================

__global__ void __launch_bounds__(256) k_w2bin(const float* __restrict__ W2) {
    size_t i = (size_t)blockIdx.x * 256 + threadIdx.x;           // one float4 -> 4 int8
    const size_t n4 = (size_t)HID * F1 / 4;
    if (i >= n4) return;
    float4 v = ((const float4*)W2)[i];
    uint32_t p = (uint32_t)(uint8_t)(int8_t)(v.x >= 0.f ? 1 : -1)
               | ((uint32_t)(uint8_t)(int8_t)(v.y >= 0.f ? 1 : -1) << 8)
               | ((uint32_t)(uint8_t)(int8_t)(v.z >= 0.f ? 1 : -1) << 16)
               | ((uint32_t)(uint8_t)(int8_t)(v.w >= 0.f ? 1 : -1) << 24);
    ((uint32_t*)g_w2b)[i] = p;
}

// =============================== kernel 2: fused conv layer ===============================
// sign(x) conv sign(W1) (pad 1) + b1 -> maxpool2x2 -> BN1 -> hardtanh -> sign -> g_act (int8 ±1)
// signs as int8 in padded smem (30x36, zero border = exact zero padding); conv via dp4a.
// All-integer hot loop: BN+sign is an int-vs-int threshold compare (exact).

__global__ void __launch_bounds__(448) k_conv(const float* __restrict__ x)
{
    __shared__ int8_t   s8[30 * 36];
    __shared__ uint32_t wpA[96], wpB[96];
    __shared__ int      ithr[32];
    __shared__ int8_t   ob[F1];

    const int tid = threadIdx.x;
    const int img = blockIdx.x;

    for (int i = tid; i < 30 * 36 / 4; i += 448) ((uint32_t*)s8)[i] = 0;
    if (tid < 96) { wpA[tid] = g_wpA[tid]; wpB[tid] = g_wpB[tid]; }
    if (tid < 32) ithr[tid] = g_ithr[tid];
    __syncthreads();

    const float* xi = x + (size_t)img * 784;
    for (int i = tid; i < 784; i += 448) {
        int h = i / 28, w = i % 28;
        s8[(h + 1) * 36 + (w + 1)] = (xi[i] >= 0.f) ? (int8_t)1 : (int8_t)-1;
    }
    __syncthreads();

    const int ch = tid / 14, ph = tid % 14;        // 32*14 = 448 threads exactly
    const uint32_t wA0 = wpA[ch*3+0], wA1 = wpA[ch*3+1], wA2 = wpA[ch*3+2];
    const uint32_t wB0 = wpB[ch*3+0], wB1 = wpB[ch*3+1], wB2 = wpB[ch*3+2];
    const int thc = ithr[ch];
    const uint32_t* r0p = (const uint32_t*)(s8 + (2*ph + 0) * 36);
    const uint32_t* r1p = (const uint32_t*)(s8 + (2*ph + 1) * 36);
    const uint32_t* r2p = (const uint32_t*)(s8 + (2*ph + 2) * 36);
    const uint32_t* r3p = (const uint32_t*)(s8 + (2*ph + 3) * 36);

    #pragma unroll 2
    for (int pw = 0; pw < 14; ++pw) {
        int cb = 2 * pw, w0 = cb >> 2;
        uint32_t win0, win1, win2, win3;
        if (cb & 2) {
            win0 = __byte_perm(r0p[w0], r0p[w0+1], 0x5432);
            win1 = __byte_perm(r1p[w0], r1p[w0+1], 0x5432);
            win2 = __byte_perm(r2p[w0], r2p[w0+1], 0x5432);
            win3 = __byte_perm(r3p[w0], r3p[w0+1], 0x5432);
        } else {
            win0 = r0p[w0]; win1 = r1p[w0]; win2 = r2p[w0]; win3 = r3p[w0];
        }
        // conv outputs (oh,ow) for oh in {2ph,2ph+1}, ow in {2pw,2pw+1}
        int c00 = __dp4a((int)win2, (int)wA2, __dp4a((int)win1, (int)wA1, __dp4a((int)win0, (int)wA0, 0)));
        int c01 = __dp4a((int)win2, (int)wB2, __dp4a((int)win1, (int)wB1, __dp4a((int)win0, (int)wB0, 0)));
        int c10 = __dp4a((int)win3, (int)wA2, __dp4a((int)win2, (int)wA1, __dp4a((int)win1, (int)wA0, 0)));
        int c11 = __dp4a((int)win3, (int)wB2, __dp4a((int)win2, (int)wB1, __dp4a((int)win1, (int)wB0, 0)));
        int mx = max(max(c00, c01), max(c10, c11));
        ob[ch * 196 + ph * 14 + pw] = (mx >= thc) ? (int8_t)1 : (int8_t)-1;
    }
    __syncthreads();

    uint32_t* dst = (uint32_t*)(g_act + (size_t)img * F1);
    const uint32_t* src = (const uint32_t*)ob;
    for (int i = tid; i < F1 / 4; i += 448) dst[i] = src[i];
}

// =============================== kernel 3: int8 mma.sync GEMM + fused epilogue ===============================
// CTA tile M=128 x N=128, 256 threads: 8 warps in 2(M)x4(N) grid, warp tile 64x32
// -> 64 acc regs/thread; __launch_bounds__(256,2) caps regs at 128 so TWO CTAs
// co-reside per SM (16 warps, occ 25%) and hide barrier/ldsm/mma latency
// (rounds 6-7: 8 warps/SM pinned tensor pipe at ~45%).
// Kc=128 int8/stage, 3-stage cp.async pipeline, ldmatrix.x4 fragments, exact s32 accum.

#define KC      128
#define NSTG    3
#define RSTR    144                   // padded smem row stride (bank-conflict-free)
#define STG_A   (128 * RSTR)          // 18432
#define STG_B   (128 * RSTR)          // 18432
#define STG_SZ  (STG_A + STG_B)       // 36864
#define GEMM_DSMEM (NSTG * STG_SZ)    // 110592

__device__ __forceinline__ void load_stage(const int8_t* A0, const int8_t* B0,
                                           uint32_t stg, int k0, int tid) {
    #pragma unroll
    for (int j = 0; j < 8; ++j) {                 // 2048 x 16B chunks / 256 threads
        int chn = tid + j * 256;
        if (chn < 1024) {                         // A: 128 rows x 8 granules
            int row = chn >> 3, c16 = chn & 7;
            cp16(stg + (uint32_t)row * RSTR + (uint32_t)c16 * 16,
                 A0 + (size_t)row * F1 + k0 + c16 * 16);
        } else {                                  // B: 128 rows x 8 granules
            int bc = chn - 1024;
            int row = bc >> 3, c16 = bc & 7;
            cp16(stg + STG_A + (uint32_t)row * RSTR + (uint32_t)c16 * 16,
                 B0 + (size_t)row * F1 + k0 + c16 * 16);
        }
    }
}

__global__ void __launch_bounds__(256, 2) k_gemm(
    const float* __restrict__ b2, const float* __restrict__ g2,
    const float* __restrict__ be2, const float* __restrict__ m2,
    const float* __restrict__ v2, const float* __restrict__ W3)
{
    extern __shared__ char dsm[];
    const uint32_t sb = smem_u32(dsm);
    const int tid = threadIdx.x, lane = tid & 31, wid = tid >> 5;
    const int wm = wid >> 2, wn = wid & 3;        // 2(M) x 4(N) warp grid, 64x32 tiles
    const int nt = blockIdx.x, mt = blockIdx.y;
    const int m0 = mt * 128, n0 = nt * 128;

    const int8_t* A0 = g_act + (size_t)m0 * F1;
    const int8_t* B0 = g_w2b + (size_t)n0 * F1;

    // prologue: stages 0,1
    load_stage(A0, B0, sb + 0 * STG_SZ, 0,  tid);
    asm volatile("cp.async.commit_group;" ::: "memory");
    load_stage(A0, B0, sb + 1 * STG_SZ, KC, tid);
    asm volatile("cp.async.commit_group;" ::: "memory");

    int acc[4][4][4];                             // [mb 16-rows][nb 8-cols][frag]
    #pragma unroll
    for (int i = 0; i < 4; ++i)
        #pragma unroll
        for (int j = 0; j < 4; ++j)
            #pragma unroll
            for (int r = 0; r < 4; ++r) acc[i][j][r] = 0;

    // ldmatrix per-thread address bases (fragment mapping validated rounds 5-7).
    const uint32_t aoffT = (uint32_t)(wm * 64 + (lane & 7) + ((lane >> 3) & 1) * 8) * RSTR
                         + ((lane >> 4) & 1) * 16;
    const uint32_t boffT = STG_A
                         + (uint32_t)(wn * 32 + (lane & 7) + ((lane >> 4) & 1) * 8) * RSTR
                         + ((lane >> 3) & 1) * 16;

    for (int k = 0; k < 49; ++k) {
        const int buf = k - (k / 3) * 3;
        asm volatile("cp.async.wait_group 1;" ::: "memory");
        __syncthreads();
        const int kn = k + 2;
        if (kn < 49) {
            const int bn = kn - (kn / 3) * 3;
            load_stage(A0, B0, sb + bn * STG_SZ, kn * KC, tid);
        }
        asm volatile("cp.async.commit_group;" ::: "memory");

        const uint32_t sA = sb + buf * STG_SZ;
        #pragma unroll
        for (int ks = 0; ks < 4; ++ks) {
            uint32_t a[4][4], b[2][4];
            #pragma unroll
            for (int mb = 0; mb < 4; ++mb)
                ldsm4(a[mb], sA + aoffT + mb * (16 * RSTR) + ks * 32);
            #pragma unroll
            for (int nbp = 0; nbp < 2; ++nbp)
                ldsm4(b[nbp], sA + boffT + nbp * (16 * RSTR) + ks * 32);
            #pragma unroll
            for (int nbp = 0; nbp < 2; ++nbp)
                #pragma unroll
                for (int mb = 0; mb < 4; ++mb) {
                    mma_s8(acc[mb][2 * nbp],     a[mb], b[nbp]);
                    mma_s8(acc[mb][2 * nbp + 1], a[mb], b[nbp] + 2);
                }
        }
    }
    __syncthreads();                                  // compute done; reuse smem

    // ---- epilogue: b2 + BN2 + hardtanh, then partial logits vs W3 ----
    float* sp = (float*)dsm;                          // [4 warp_n][128 rows][10] = 20 KB
    float* tb = (float*)(dsm + 20480);                // tables: 5*128 + 128*10 floats
    if (tid < 128) {
        int n = n0 + tid;
        tb[tid]       = b2[n];
        tb[128 + tid] = g2[n];
        tb[256 + tid] = m2[n];
        tb[384 + tid] = 1.0f / sqrtf(v2[n] + EPSV);
        tb[512 + tid] = be2[n];
    }
    for (int i = tid; i < 1280; i += 256) {
        int col = i / 10, c = i - col * 10;
        tb[640 + i] = W3[(size_t)c * HID + n0 + col];
    }
    __syncthreads();

    #pragma unroll
    for (int mb = 0; mb < 4; ++mb) {
        #pragma unroll
        for (int half = 0; half < 2; ++half) {
            int row = wm * 64 + mb * 16 + (lane >> 2) + 8 * half;
            float l10[NCLS];
            #pragma unroll
            for (int c = 0; c < NCLS; ++c) l10[c] = 0.f;
            #pragma unroll
            for (int nb = 0; nb < 4; ++nb) {
                #pragma unroll
                for (int e = 0; e < 2; ++e) {
                    int col = wn * 32 + nb * 8 + 2 * (lane & 3) + e;
                    float z = (float)acc[mb][nb][half * 2 + e] + tb[col];   // + b2 (exact int)
                    float t = tb[128 + col] * (z - tb[256 + col]);          // g2*(z-m2)
                    t *= tb[384 + col]; t += tb[512 + col];                 // *rs + be2
                    t = fminf(1.f, fmaxf(-1.f, t));                         // hardtanh
                    const float* w3c = tb + 640 + col * 10;
                    #pragma unroll
                    for (int c = 0; c < NCLS; ++c) l10[c] = fmaf(t, w3c[c], l10[c]);
                }
            }
            #pragma unroll
            for (int c = 0; c < NCLS; ++c) {
                l10[c] += __shfl_xor_sync(0xffffffffu, l10[c], 1);
                l10[c] += __shfl_xor_sync(0xffffffffu, l10[c], 2);
            }
            if ((lane & 3) == 0) {
                float* d = sp + ((size_t)wn * 128 + row) * NCLS;
                #pragma unroll
                for (int c = 0; c < NCLS; ++c) d[c] = l10[c];
            }
        }
    }
    __syncthreads();

    for (int i = tid; i < 128 * NCLS; i += 256) {
        int row = i / NCLS, c = i - row * NCLS;
        float s = sp[(0 * 128 + row) * NCLS + c] + sp[(1 * 128 + row) * NCLS + c]
                + sp[(2 * 128 + row) * NCLS + c] + sp[(3 * 128 + row) * NCLS + c];
        g_part[((size_t)nt * B_SZ + m0 + row) * NCLS + c] = s;
    }
}

// =============================== kernel 4: reduce + b3 + log_softmax ===============================

__global__ void __launch_bounds__(256) k_final(const float* __restrict__ b3,
                                               float* __restrict__ out) {
    int row = blockIdx.x * 256 + threadIdx.x;     // 4096 rows
    float l[NCLS];
    #pragma unroll
    for (int c = 0; c < NCLS; ++c) l[c] = b3[c];
    #pragma unroll
    for (int p = 0; p < 16; ++p) {
        const float* s = g_part + ((size_t)p * B_SZ + row) * NCLS;
        #pragma unroll
        for (int c = 0; c < NCLS; ++c) l[c] += s[c];
    }
    float m = l[0];
    #pragma unroll
    for (int c = 1; c < NCLS; ++c) m = fmaxf(m, l[c]);
    float sum = 0.f;
    #pragma unroll
    for (int c = 0; c < NCLS; ++c) sum += expf(l[c] - m);
    float lse = m + logf(sum);
    #pragma unroll
    for (int c = 0; c < NCLS; ++c) out[row * NCLS + c] = l[c] - lse;
}

// =============================== launcher ===============================

extern "C" void kernel_launch(void* const* d_in, const int* in_sizes, int n_in,
                              void* d_out, int out_size) {
    const float* x   = (const float*)d_in[0];
    const float* W1  = (const float*)d_in[1];
    const float* b1  = (const float*)d_in[2];
    const float* g1  = (const float*)d_in[3];
    const float* be1 = (const float*)d_in[4];
    const float* m1  = (const float*)d_in[5];
    const float* v1  = (const float*)d_in[6];
    const float* W2  = (const float*)d_in[7];
    const float* b2  = (const float*)d_in[8];
    const float* g2  = (const float*)d_in[9];
    const float* be2 = (const float*)d_in[10];
    const float* m2  = (const float*)d_in[11];
    const float* v2  = (const float*)d_in[12];
    const float* W3  = (const float*)d_in[13];
    const float* b3  = (const float*)d_in[14];

    cudaFuncSetAttribute(k_gemm, cudaFuncAttributeMaxDynamicSharedMemorySize, GEMM_DSMEM);

    k_prep<<<1, 96>>>(W1, b1, g1, be1, m1, v1);
    k_w2bin<<<(int)(((size_t)HID * F1 / 4 + 255) / 256), 256>>>(W2);
    k_conv<<<B_SZ, 448>>>(x);
    k_gemm<<<dim3(16, 32), 256, GEMM_DSMEM>>>(b2, g2, be2, m2, v2, W3);
    k_final<<<16, 256>>>(b3, (float*)d_out);
}

// round 9
// speedup vs baseline: 1.0308x; 1.0308x over previous
#include <cuda_runtime.h>
#include <cstdint>
#include <math.h>

#define B_SZ   4096
#define F1     6272          // 32*14*14
#define HID    2048
#define NCLS   10
#define EPSV   1e-5f

// ---------------- static device scratch (no runtime allocation) ----------------
__device__ __align__(16) int8_t g_act[(size_t)B_SZ * F1];   // 25.7 MB, ±1
__device__ __align__(16) int8_t g_w2b[(size_t)HID  * F1];   // 12.8 MB, ±1
__device__ float g_part[(size_t)16 * B_SZ * NCLS];          // 2.6 MB partial logits
__device__ uint32_t g_wpA[96], g_wpB[96];                   // conv weight byte-packs
__device__ int      g_ithr[32];                             // integer sign thresholds

// =============================== helpers ===============================

__device__ __forceinline__ uint32_t smem_u32(const void* p) {
    return (uint32_t)__cvta_generic_to_shared(p);
}

__device__ __forceinline__ void cp16(uint32_t dst, const void* src) {
    asm volatile("cp.async.cg.shared.global [%0], [%1], 16;"
                 :: "r"(dst), "l"(src) : "memory");
}

__device__ __forceinline__ void mma_s8(int* d, const uint32_t* a, const uint32_t* b) {
    asm volatile(
        "mma.sync.aligned.m16n8k32.row.col.s32.s8.s8.s32 "
        "{%0,%1,%2,%3}, {%4,%5,%6,%7}, {%8,%9}, {%0,%1,%2,%3};"
        : "+r"(d[0]), "+r"(d[1]), "+r"(d[2]), "+r"(d[3])
        : "r"(a[0]), "r"(a[1]), "r"(a[2]), "r"(a[3]), "r"(b[0]), "r"(b[1]));
}

__device__ __forceinline__ void ldsm4(uint32_t* r, uint32_t addr) {
    asm volatile("ldmatrix.sync.aligned.m8n8.x4.shared.b16 {%0,%1,%2,%3}, [%4];"
                 : "=r"(r[0]), "=r"(r[1]), "=r"(r[2]), "=r"(r[3]) : "r"(addr));
}

// =============================== kernel 0: conv constants prep (once) ===============================

__global__ void __launch_bounds__(96) k_prep(
    const float* __restrict__ W1, const float* __restrict__ b1,
    const float* __restrict__ g1, const float* __restrict__ be1,
    const float* __restrict__ m1, const float* __restrict__ v1)
{
    int t = threadIdx.x;
    if (t < 96) {       // per-channel weight-row byte packs (A: bytes0-2, B: bytes1-3)
        int ch = t / 3, j = t % 3;
        const float* wr = W1 + ch * 9 + j * 3;
        uint32_t b0 = (uint8_t)(int8_t)(wr[0] >= 0.f ? 1 : -1);
        uint32_t bb = (uint8_t)(int8_t)(wr[1] >= 0.f ? 1 : -1);
        uint32_t b2 = (uint8_t)(int8_t)(wr[2] >= 0.f ? 1 : -1);
        g_wpA[t] = b0 | (bb << 8) | (b2 << 16);
        g_wpB[t] = (b0 << 8) | (bb << 16) | (b2 << 24);
    }
    if (t < 32) {
        // sign(BN(pool(conv)+b1)) == (mx >= thr), thr = m1 - be1*sqrt(v1+eps)/g1 - b1 (g1>0)
        // mx is an exact integer in [-9,9] => integer threshold ceil(thr) is exact.
        double sq = sqrt((double)v1[t] + (double)EPSV);
        double thr = (double)m1[t] - (double)be1[t] * sq / (double)g1[t] - (double)b1[t];
        g_ithr[t] = (int)ceil(thr);
    }
}

// =============================== kernel 1: W2 sign-pack (f32 -> int8 ±1) ===============================

__global__ void __launch_bounds__(256) k_w2bin(const float* __restrict__ W2) {
    size_t i = (size_t)blockIdx.x * 256 + threadIdx.x;           // one float4 -> 4 int8
    const size_t n4 = (size_t)HID * F1 / 4;
    if (i >= n4) return;
    float4 v = ((const float4*)W2)[i];
    uint32_t p = (uint32_t)(uint8_t)(int8_t)(v.x >= 0.f ? 1 : -1)
               | ((uint32_t)(uint8_t)(int8_t)(v.y >= 0.f ? 1 : -1) << 8)
               | ((uint32_t)(uint8_t)(int8_t)(v.z >= 0.f ? 1 : -1) << 16)
               | ((uint32_t)(uint8_t)(int8_t)(v.w >= 0.f ? 1 : -1) << 24);
    ((uint32_t*)g_w2b)[i] = p;
}

// =============================== kernel 2: fused conv layer ===============================
// sign(x) conv sign(W1) (pad 1) + b1 -> maxpool2x2 -> BN1 -> hardtanh -> sign -> g_act (int8 ±1)
// signs as int8 in padded smem (30x36, zero border = exact zero padding); conv via dp4a.
// All-integer hot loop: BN+sign is an int-vs-int threshold compare (exact).

__global__ void __launch_bounds__(448) k_conv(const float* __restrict__ x)
{
    __shared__ int8_t   s8[30 * 36];
    __shared__ uint32_t wpA[96], wpB[96];
    __shared__ int      ithr[32];
    __shared__ int8_t   ob[F1];

    const int tid = threadIdx.x;
    const int img = blockIdx.x;

    for (int i = tid; i < 30 * 36 / 4; i += 448) ((uint32_t*)s8)[i] = 0;
    if (tid < 96) { wpA[tid] = g_wpA[tid]; wpB[tid] = g_wpB[tid]; }
    if (tid < 32) ithr[tid] = g_ithr[tid];
    __syncthreads();

    const float* xi = x + (size_t)img * 784;
    for (int i = tid; i < 784; i += 448) {
        int h = i / 28, w = i % 28;
        s8[(h + 1) * 36 + (w + 1)] = (xi[i] >= 0.f) ? (int8_t)1 : (int8_t)-1;
    }
    __syncthreads();

    const int ch = tid / 14, ph = tid % 14;        // 32*14 = 448 threads exactly
    const uint32_t wA0 = wpA[ch*3+0], wA1 = wpA[ch*3+1], wA2 = wpA[ch*3+2];
    const uint32_t wB0 = wpB[ch*3+0], wB1 = wpB[ch*3+1], wB2 = wpB[ch*3+2];
    const int thc = ithr[ch];
    const uint32_t* r0p = (const uint32_t*)(s8 + (2*ph + 0) * 36);
    const uint32_t* r1p = (const uint32_t*)(s8 + (2*ph + 1) * 36);
    const uint32_t* r2p = (const uint32_t*)(s8 + (2*ph + 2) * 36);
    const uint32_t* r3p = (const uint32_t*)(s8 + (2*ph + 3) * 36);

    #pragma unroll 2
    for (int pw = 0; pw < 14; ++pw) {
        int cb = 2 * pw, w0 = cb >> 2;
        uint32_t win0, win1, win2, win3;
        if (cb & 2) {
            win0 = __byte_perm(r0p[w0], r0p[w0+1], 0x5432);
            win1 = __byte_perm(r1p[w0], r1p[w0+1], 0x5432);
            win2 = __byte_perm(r2p[w0], r2p[w0+1], 0x5432);
            win3 = __byte_perm(r3p[w0], r3p[w0+1], 0x5432);
        } else {
            win0 = r0p[w0]; win1 = r1p[w0]; win2 = r2p[w0]; win3 = r3p[w0];
        }
        // conv outputs (oh,ow) for oh in {2ph,2ph+1}, ow in {2pw,2pw+1}
        int c00 = __dp4a((int)win2, (int)wA2, __dp4a((int)win1, (int)wA1, __dp4a((int)win0, (int)wA0, 0)));
        int c01 = __dp4a((int)win2, (int)wB2, __dp4a((int)win1, (int)wB1, __dp4a((int)win0, (int)wB0, 0)));
        int c10 = __dp4a((int)win3, (int)wA2, __dp4a((int)win2, (int)wA1, __dp4a((int)win1, (int)wA0, 0)));
        int c11 = __dp4a((int)win3, (int)wB2, __dp4a((int)win2, (int)wB1, __dp4a((int)win1, (int)wB0, 0)));
        int mx = max(max(c00, c01), max(c10, c11));
        ob[ch * 196 + ph * 14 + pw] = (mx >= thc) ? (int8_t)1 : (int8_t)-1;
    }
    __syncthreads();

    uint32_t* dst = (uint32_t*)(g_act + (size_t)img * F1);
    const uint32_t* src = (const uint32_t*)ob;
    for (int i = tid; i < F1 / 4; i += 448) dst[i] = src[i];
}

// =============================== kernel 3: int8 mma.sync GEMM + fused epilogue ===============================
// CTA tile M=128 x N=128, 256 threads: 8 warps in 2(M)x4(N) grid, warp tile 64x32.
// 2 CTAs/SM. Round-8 ncu: tensor and L1 both ~45% => ldsm and mma phases ALTERNATE
// (barrier phase-locks all warps: ldsm burst then mma burst). Fix: software-pipeline
// fragments across the 4 ks-steps (double-buffered regs) so the smem crossbar runs
// concurrently with the tensor pipe. Exact s32 accumulation, bit-identical output.

#define KC      128
#define NSTG    3
#define RSTR    144                   // padded smem row stride (bank-conflict-free)
#define STG_A   (128 * RSTR)          // 18432
#define STG_B   (128 * RSTR)          // 18432
#define STG_SZ  (STG_A + STG_B)       // 36864
#define GEMM_DSMEM (NSTG * STG_SZ)    // 110592

__device__ __forceinline__ void load_stage(const int8_t* A0, const int8_t* B0,
                                           uint32_t stg, int k0, int tid) {
    #pragma unroll
    for (int j = 0; j < 8; ++j) {                 // 2048 x 16B chunks / 256 threads
        int chn = tid + j * 256;
        if (chn < 1024) {                         // A: 128 rows x 8 granules
            int row = chn >> 3, c16 = chn & 7;
            cp16(stg + (uint32_t)row * RSTR + (uint32_t)c16 * 16,
                 A0 + (size_t)row * F1 + k0 + c16 * 16);
        } else {                                  // B: 128 rows x 8 granules
            int bc = chn - 1024;
            int row = bc >> 3, c16 = bc & 7;
            cp16(stg + STG_A + (uint32_t)row * RSTR + (uint32_t)c16 * 16,
                 B0 + (size_t)row * F1 + k0 + c16 * 16);
        }
    }
}

__global__ void __launch_bounds__(256, 2) k_gemm(
    const float* __restrict__ b2, const float* __restrict__ g2,
    const float* __restrict__ be2, const float* __restrict__ m2,
    const float* __restrict__ v2, const float* __restrict__ W3)
{
    extern __shared__ char dsm[];
    const uint32_t sb = smem_u32(dsm);
    const int tid = threadIdx.x, lane = tid & 31, wid = tid >> 5;
    const int wm = wid >> 2, wn = wid & 3;        // 2(M) x 4(N) warp grid, 64x32 tiles
    const int nt = blockIdx.x, mt = blockIdx.y;
    const int m0 = mt * 128, n0 = nt * 128;

    const int8_t* A0 = g_act + (size_t)m0 * F1;
    const int8_t* B0 = g_w2b + (size_t)n0 * F1;

    // prologue: stages 0,1
    load_stage(A0, B0, sb + 0 * STG_SZ, 0,  tid);
    asm volatile("cp.async.commit_group;" ::: "memory");
    load_stage(A0, B0, sb + 1 * STG_SZ, KC, tid);
    asm volatile("cp.async.commit_group;" ::: "memory");

    int acc[4][4][4];                             // [mb 16-rows][nb 8-cols][frag]
    #pragma unroll
    for (int i = 0; i < 4; ++i)
        #pragma unroll
        for (int j = 0; j < 4; ++j)
            #pragma unroll
            for (int r = 0; r < 4; ++r) acc[i][j][r] = 0;

    // ldmatrix per-thread address bases (fragment mapping validated rounds 5-8).
    const uint32_t aoffT = (uint32_t)(wm * 64 + (lane & 7) + ((lane >> 3) & 1) * 8) * RSTR
                         + ((lane >> 4) & 1) * 16;
    const uint32_t boffT = STG_A
                         + (uint32_t)(wn * 32 + (lane & 7) + ((lane >> 4) & 1) * 8) * RSTR
                         + ((lane >> 3) & 1) * 16;

    for (int k = 0; k < 49; ++k) {
        const int buf = k - (k / 3) * 3;
        asm volatile("cp.async.wait_group 1;" ::: "memory");
        __syncthreads();
        const int kn = k + 2;
        if (kn < 49) {
            const int bn = kn - (kn / 3) * 3;
            load_stage(A0, B0, sb + bn * STG_SZ, kn * KC, tid);
        }
        asm volatile("cp.async.commit_group;" ::: "memory");

        const uint32_t sA = sb + buf * STG_SZ;

        // software-pipelined fragment loads across ks-steps (double-buffered regs):
        // ldsm for ks+1 issues before the mmas of ks, overlapping crossbar w/ tensor.
        uint32_t a[2][4][4], b[2][2][4];
        #pragma unroll
        for (int mb = 0; mb < 4; ++mb)
            ldsm4(a[0][mb], sA + aoffT + mb * (16 * RSTR));
        #pragma unroll
        for (int nbp = 0; nbp < 2; ++nbp)
            ldsm4(b[0][nbp], sA + boffT + nbp * (16 * RSTR));

        #pragma unroll
        for (int ks = 0; ks < 4; ++ks) {
            const int cur = ks & 1, nxt = cur ^ 1;
            if (ks < 3) {
                #pragma unroll
                for (int mb = 0; mb < 4; ++mb)
                    ldsm4(a[nxt][mb], sA + aoffT + mb * (16 * RSTR) + (ks + 1) * 32);
                #pragma unroll
                for (int nbp = 0; nbp < 2; ++nbp)
                    ldsm4(b[nxt][nbp], sA + boffT + nbp * (16 * RSTR) + (ks + 1) * 32);
            }
            #pragma unroll
            for (int nbp = 0; nbp < 2; ++nbp)
                #pragma unroll
                for (int mb = 0; mb < 4; ++mb) {
                    mma_s8(acc[mb][2 * nbp],     a[cur][mb], b[cur][nbp]);
                    mma_s8(acc[mb][2 * nbp + 1], a[cur][mb], b[cur][nbp] + 2);
                }
        }
    }
    __syncthreads();                                  // compute done; reuse smem

    // ---- epilogue: b2 + BN2 + hardtanh, then partial logits vs W3 ----
    float* sp = (float*)dsm;                          // [4 warp_n][128 rows][10] = 20 KB
    float* tb = (float*)(dsm + 20480);                // tables: 5*128 + 128*10 floats
    if (tid < 128) {
        int n = n0 + tid;
        tb[tid]       = b2[n];
        tb[128 + tid] = g2[n];
        tb[256 + tid] = m2[n];
        tb[384 + tid] = 1.0f / sqrtf(v2[n] + EPSV);
        tb[512 + tid] = be2[n];
    }
    for (int i = tid; i < 1280; i += 256) {
        int col = i / 10, c = i - col * 10;
        tb[640 + i] = W3[(size_t)c * HID + n0 + col];
    }
    __syncthreads();

    #pragma unroll
    for (int mb = 0; mb < 4; ++mb) {
        #pragma unroll
        for (int half = 0; half < 2; ++half) {
            int row = wm * 64 + mb * 16 + (lane >> 2) + 8 * half;
            float l10[NCLS];
            #pragma unroll
            for (int c = 0; c < NCLS; ++c) l10[c] = 0.f;
            #pragma unroll
            for (int nb = 0; nb < 4; ++nb) {
                #pragma unroll
                for (int e = 0; e < 2; ++e) {
                    int col = wn * 32 + nb * 8 + 2 * (lane & 3) + e;
                    float z = (float)acc[mb][nb][half * 2 + e] + tb[col];   // + b2 (exact int)
                    float t = tb[128 + col] * (z - tb[256 + col]);          // g2*(z-m2)
                    t *= tb[384 + col]; t += tb[512 + col];                 // *rs + be2
                    t = fminf(1.f, fmaxf(-1.f, t));                         // hardtanh
                    const float* w3c = tb + 640 + col * 10;
                    #pragma unroll
                    for (int c = 0; c < NCLS; ++c) l10[c] = fmaf(t, w3c[c], l10[c]);
                }
            }
            #pragma unroll
            for (int c = 0; c < NCLS; ++c) {
                l10[c] += __shfl_xor_sync(0xffffffffu, l10[c], 1);
                l10[c] += __shfl_xor_sync(0xffffffffu, l10[c], 2);
            }
            if ((lane & 3) == 0) {
                float* d = sp + ((size_t)wn * 128 + row) * NCLS;
                #pragma unroll
                for (int c = 0; c < NCLS; ++c) d[c] = l10[c];
            }
        }
    }
    __syncthreads();

    for (int i = tid; i < 128 * NCLS; i += 256) {
        int row = i / NCLS, c = i - row * NCLS;
        float s = sp[(0 * 128 + row) * NCLS + c] + sp[(1 * 128 + row) * NCLS + c]
                + sp[(2 * 128 + row) * NCLS + c] + sp[(3 * 128 + row) * NCLS + c];
        g_part[((size_t)nt * B_SZ + m0 + row) * NCLS + c] = s;
    }
}

// =============================== kernel 4: reduce + b3 + log_softmax ===============================

__global__ void __launch_bounds__(256) k_final(const float* __restrict__ b3,
                                               float* __restrict__ out) {
    int row = blockIdx.x * 256 + threadIdx.x;     // 4096 rows
    float l[NCLS];
    #pragma unroll
    for (int c = 0; c < NCLS; ++c) l[c] = b3[c];
    #pragma unroll
    for (int p = 0; p < 16; ++p) {
        const float* s = g_part + ((size_t)p * B_SZ + row) * NCLS;
        #pragma unroll
        for (int c = 0; c < NCLS; ++c) l[c] += s[c];
    }
    float m = l[0];
    #pragma unroll
    for (int c = 1; c < NCLS; ++c) m = fmaxf(m, l[c]);
    float sum = 0.f;
    #pragma unroll
    for (int c = 0; c < NCLS; ++c) sum += expf(l[c] - m);
    float lse = m + logf(sum);
    #pragma unroll
    for (int c = 0; c < NCLS; ++c) out[row * NCLS + c] = l[c] - lse;
}

// =============================== launcher ===============================

extern "C" void kernel_launch(void* const* d_in, const int* in_sizes, int n_in,
                              void* d_out, int out_size) {
    const float* x   = (const float*)d_in[0];
    const float* W1  = (const float*)d_in[1];
    const float* b1  = (const float*)d_in[2];
    const float* g1  = (const float*)d_in[3];
    const float* be1 = (const float*)d_in[4];
    const float* m1  = (const float*)d_in[5];
    const float* v1  = (const float*)d_in[6];
    const float* W2  = (const float*)d_in[7];
    const float* b2  = (const float*)d_in[8];
    const float* g2  = (const float*)d_in[9];
    const float* be2 = (const float*)d_in[10];
    const float* m2  = (const float*)d_in[11];
    const float* v2  = (const float*)d_in[12];
    const float* W3  = (const float*)d_in[13];
    const float* b3  = (const float*)d_in[14];

    cudaFuncSetAttribute(k_gemm, cudaFuncAttributeMaxDynamicSharedMemorySize, GEMM_DSMEM);

    k_prep<<<1, 96>>>(W1, b1, g1, be1, m1, v1);
    k_w2bin<<<(int)(((size_t)HID * F1 / 4 + 255) / 256), 256>>>(W2);
    k_conv<<<B_SZ, 448>>>(x);
    k_gemm<<<dim3(16, 32), 256, GEMM_DSMEM>>>(b2, g2, be2, m2, v2, W3);
    k_final<<<16, 256>>>(b3, (float*)d_out);
}